// round 16
// baseline (speedup 1.0000x reference)
#include <cuda_runtime.h>

#define TW 32
#define TH 52
#define HALO 5
#define RW (TW + 2*HALO)      // 42
#define RH (TH + 2*HALO)      // 62
#define NT 512
#define IMG 512
#define PLANE (IMG*IMG)
#define GRIDY ((IMG + TH - 1) / TH)   // 10 (last tile partial)

#define SSIM_C1 0.0001f
#define SSIM_C2 0.0009f

#define HBS 33                // hb row stride in float4 (padded)
// smem: float2 raw[RH*RW] = 20832 B ; float4 hb[RH*HBS] = 32736 B ; 53568 B
// -> 4 CTAs/SM x 512 threads = 2048 threads (100% occupancy)
#define RAW_N (RH*RW)
#define RAW4_N (RAW_N/2)      // 1302 float4 slots (21 pairs per row)
#define SMEM_BYTES (RAW_N*8 + RH*HBS*16)

// 11-tap gaussian, sigma=1.5, normalized; symmetric
__device__ __forceinline__ constexpr float wk(int k) {
    constexpr float W6[6] = { 0.00102838f, 0.00759876f, 0.03600077f,
                              0.10936078f, 0.21300553f, 0.26601171f };
    return W6[k < 6 ? k : 10 - k];
}

__global__ void __launch_bounds__(NT, 4)
ssim_kernel(const float* __restrict__ x, const float* __restrict__ y,
            float* __restrict__ out)
{
    extern __shared__ float smem[];
    float4* raw4 = (float4*)smem;                // RAW4_N {x0,y0,x1,y1}
    float4* hb4  = (float4*)(smem + RAW_N*2);    // RH*HBS {hx,hy,hs,hxy}

    const int tid   = threadIdx.x;
    const int bx    = blockIdx.x;                // 0..15
    const int by    = blockIdx.y;                // 0..9
    const int plane = blockIdx.z;                // 0..47

    const float* __restrict__ xp = x + (size_t)plane * PLANE;
    const float* __restrict__ yp = y + (size_t)plane * PLANE;

    const int gx0 = bx * TW - HALO;
    const int gy0 = by * TH - HALO;

    const bool interior = (gx0 >= 0) & (gy0 >= 0) &
                          (gx0 + RW <= IMG) & (gy0 + RH <= IMG);

    // ---------------- Stage 1: gmem -> smem raw tile ----------------------
    if (interior) {
        const int base = gy0 * IMG + gx0;        // block-uniform
        // 1302 flat float4 tasks; slot i <-> (r = i/21, pair = i%21)
        #pragma unroll
        for (int rep = 0; rep < 3; ++rep) {
            const int i = tid + rep * NT;
            if (rep < 2 || i < RAW4_N) {
                const int r  = i / 21;           // const-div -> mulhi
                const int cc = (i - r * 21) * 2;
                const int off = base + r * IMG + cc;
                float x0 = __ldg(xp + off);
                float x1 = __ldg(xp + off + 1);
                float y0 = __ldg(yp + off);
                float y1 = __ldg(yp + off + 1);
                raw4[i] = make_float4(x0, y0, x1, y1);
            }
        }
    } else {
        #pragma unroll 1
        for (int i = tid; i < RAW4_N; i += NT) {
            const int r  = i / 21;
            const int cc = (i - r * 21) * 2;
            const int gr = gy0 + r;
            const int gc0 = gx0 + cc;
            float x0 = 0.f, x1 = 0.f, y0 = 0.f, y1 = 0.f;
            if ((unsigned)gr < (unsigned)IMG) {
                const int rb = gr * IMG;
                if ((unsigned)gc0 < (unsigned)IMG) {
                    x0 = __ldg(xp + rb + gc0);
                    y0 = __ldg(yp + rb + gc0);
                }
                if ((unsigned)(gc0+1) < (unsigned)IMG) {
                    x1 = __ldg(xp + rb + gc0 + 1);
                    y1 = __ldg(yp + rb + gc0 + 1);
                }
            }
            raw4[i] = make_float4(x0, y0, x1, y1);
        }
    }
    __syncthreads();

    // ---------------- Stage 2: horizontal 11-tap, 4-col register block ----
    // 8 col-groups x 62 rows = 496 tasks, single pass; lanes map to
    // consecutive ROWS within a group -> conflict-free LDS/STS phases.
    if (tid < 8*RH) {
        const int gq  = tid / RH;            // column group 0..7
        const int row = tid - gq * RH;       // 0..61
        // raw float4 slot index: row*21 + 2*gq
        const float4* rp4 = raw4 + row * 21 + 2 * gq;

        // acc[i2] = {hx, hy, hs, hxy} accumulated in-place (STS.128 source)
        float4 acc[4];
        #pragma unroll
        for (int i2 = 0; i2 < 4; ++i2) acc[i2] = make_float4(0.f,0.f,0.f,0.f);

        #pragma unroll
        for (int q = 0; q < 7; ++q) {        // 7 x LDS.128 = 14 taps
            float4 pr = rp4[q];              // {x0,y0,x1,y1} = taps 2q, 2q+1
            #pragma unroll
            for (int h = 0; h < 2; ++h) {
                const int p = 2*q + h;
                float vx = h ? pr.z : pr.x;
                float vy = h ? pr.w : pr.y;
                float s  = fmaf(vy, vy, vx * vx);
                float xy = vx * vy;
                #pragma unroll
                for (int i2 = 0; i2 < 4; ++i2) {
                    int k = p - i2;
                    if (k >= 0 && k <= 10) {
                        acc[i2].x = fmaf(vx, wk(k), acc[i2].x);
                        acc[i2].y = fmaf(vy, wk(k), acc[i2].y);
                        acc[i2].z = fmaf(s,  wk(k), acc[i2].z);
                        acc[i2].w = fmaf(xy, wk(k), acc[i2].w);
                    }
                }
            }
        }

        float4* hp = hb4 + row * HBS + 4*gq;
        #pragma unroll
        for (int i2 = 0; i2 < 4; ++i2)
            hp[i2] = acc[i2];
    }
    __syncthreads();

    // ---------------- Stage 3: vertical 11-tap, 4-row block, LDS.128 taps -
    // 32 cols x 13 segments = 416 tasks on threads 0..415.
    if (tid < 32*(TH/4)) {
        const int col = tid & 31;
        const int r0  = (tid >> 5) * 4;     // 13 segments * 4 rows = 52

        float b0[4] = {0,0,0,0}, b1[4] = {0,0,0,0},
              b2[4] = {0,0,0,0}, b3[4] = {0,0,0,0};

        const float4* hp = hb4 + r0 * HBS + col;
        #pragma unroll
        for (int p = 0; p < 14; ++p) {
            float4 h = hp[p * HBS];          // one LDS.128: all 4 quantities
            #pragma unroll
            for (int i2 = 0; i2 < 4; ++i2) {
                int k = p - i2;
                if (k >= 0 && k <= 10) {
                    b0[i2] = fmaf(h.x, wk(k), b0[i2]);
                    b1[i2] = fmaf(h.y, wk(k), b1[i2]);
                    b2[i2] = fmaf(h.z, wk(k), b2[i2]);
                    b3[i2] = fmaf(h.w, wk(k), b3[i2]);
                }
            }
        }

        const int row_out0 = by * TH + r0;
        float* op = out + (size_t)plane * PLANE
                        + (size_t)row_out0 * IMG
                        + bx * TW + col;

        #pragma unroll
        for (int i2 = 0; i2 < 4; ++i2) {
            if (row_out0 + i2 < IMG) {       // last row-tile is partial
                float mu1  = b0[i2];
                float mu2  = b1[i2];
                float m12  = mu1 * mu2;
                float m11  = mu1 * mu1;
                float m22  = mu2 * mu2;
                float ssum = b2[i2] - m11 - m22;    // sigma1^2 + sigma2^2
                float s12  = b3[i2] - m12;
                float num = fmaf(2.f, m12, SSIM_C1) * fmaf(2.f, s12, SSIM_C2);
                float den = (m11 + m22 + SSIM_C1) * (ssum + SSIM_C2);
                op[(size_t)i2 * IMG] = __fdividef(num, den);
            }
        }
    }
}

extern "C" void kernel_launch(void* const* d_in, const int* in_sizes, int n_in,
                              void* d_out, int out_size)
{
    const float* x = (const float*)d_in[0];   // img_out  [16,3,512,512] f32
    const float* y = (const float*)d_in[1];   // img_target
    float* out = (float*)d_out;

    int planes = in_sizes[0] / PLANE;         // 48

    cudaFuncSetAttribute(ssim_kernel,
                         cudaFuncAttributeMaxDynamicSharedMemorySize,
                         SMEM_BYTES);

    dim3 grid(IMG / TW, GRIDY, planes);       // (16, 10, 48)
    ssim_kernel<<<grid, NT, SMEM_BYTES>>>(x, y, out);
}

// round 17
// speedup vs baseline: 1.1239x; 1.1239x over previous
#include <cuda_runtime.h>

#define TW 32
#define TH 32
#define HALO 5
#define RW (TW + 2*HALO)      // 42
#define RH (TH + 2*HALO)      // 42
#define NT 384
#define IMG 512
#define PLANE (IMG*IMG)

#define SSIM_C1 0.0001f
#define SSIM_C2 0.0009f

#define HBS 33                // hb row stride in float4 (padded)
// smem: float2 raw[RH*RW] = 14112 B ; float4 hb[RH*HBS] = 22176 B ; 36288 B
// -> 5 CTAs/SM x 384 threads = 1920 threads/SM
#define RAW_N (RH*RW)
#define RAW4_N (RAW_N/2)      // 882 float4 slots (21 pairs per row)
#define SMEM_BYTES (RAW_N*8 + RH*HBS*16)

// 11-tap gaussian, sigma=1.5, normalized; symmetric
__device__ __forceinline__ constexpr float wk(int k) {
    constexpr float W6[6] = { 0.00102838f, 0.00759876f, 0.03600077f,
                              0.10936078f, 0.21300553f, 0.26601171f };
    return W6[k < 6 ? k : 10 - k];
}

__global__ void __launch_bounds__(NT, 5)
ssim_kernel(const float* __restrict__ x, const float* __restrict__ y,
            float* __restrict__ out)
{
    extern __shared__ float smem[];
    float4* raw4 = (float4*)smem;                // RAW4_N {x0,y0,x1,y1}
    float4* hb4  = (float4*)(smem + RAW_N*2);    // RH*HBS {hx,hy,hs,hxy}

    const int tid   = threadIdx.x;
    const int bx    = blockIdx.x;                // 0..15
    const int by    = blockIdx.y;                // 0..15
    const int plane = blockIdx.z;                // 0..47

    const float* __restrict__ xp = x + (size_t)plane * PLANE;
    const float* __restrict__ yp = y + (size_t)plane * PLANE;

    const int gx0 = bx * TW - HALO;
    const int gy0 = by * TH - HALO;

    const bool interior = (gx0 >= 0) & (gy0 >= 0) &
                          (gx0 + RW <= IMG) & (gy0 + RH <= IMG);

    // ---------------- Stage 1: gmem -> smem raw tile ----------------------
    if (interior) {
        const int base = gy0 * IMG + gx0;        // block-uniform
        // 882 flat float4 tasks; slot i <-> (r = i/21, pair = i%21)
        #pragma unroll
        for (int rep = 0; rep < 3; ++rep) {
            const int i = tid + rep * NT;
            if (rep < 2 || i < RAW4_N) {
                const int r  = i / 21;           // const-div -> mulhi
                const int cc = (i - r * 21) * 2;
                const int off = base + r * IMG + cc;
                float x0 = __ldg(xp + off);
                float x1 = __ldg(xp + off + 1);
                float y0 = __ldg(yp + off);
                float y1 = __ldg(yp + off + 1);
                raw4[i] = make_float4(x0, y0, x1, y1);
            }
        }
    } else {
        #pragma unroll 1
        for (int i = tid; i < RAW4_N; i += NT) {
            const int r  = i / 21;
            const int cc = (i - r * 21) * 2;
            const int gr = gy0 + r;
            const int gc0 = gx0 + cc;
            float x0 = 0.f, x1 = 0.f, y0 = 0.f, y1 = 0.f;
            if ((unsigned)gr < (unsigned)IMG) {
                const int rb = gr * IMG;
                if ((unsigned)gc0 < (unsigned)IMG) {
                    x0 = __ldg(xp + rb + gc0);
                    y0 = __ldg(yp + rb + gc0);
                }
                if ((unsigned)(gc0+1) < (unsigned)IMG) {
                    x1 = __ldg(xp + rb + gc0 + 1);
                    y1 = __ldg(yp + rb + gc0 + 1);
                }
            }
            raw4[i] = make_float4(x0, y0, x1, y1);
        }
    }
    __syncthreads();

    // ---------------- Stage 2: horizontal 11-tap, 4-col register block ----
    // 8 col-groups x 42 rows = 336 tasks, single pass (336/384 active);
    // lanes map to consecutive ROWS within a group -> conflict-free phases.
    if (tid < 8*RH) {
        const int gq  = tid / RH;            // column group 0..7
        const int row = tid - gq * RH;       // 0..41
        // raw float4 slot index: (row*RW + 4*gq)/2 = row*21 + 2*gq
        const float4* rp4 = raw4 + row * 21 + 2 * gq;

        // acc[i2] = {hx, hy, hs, hxy} accumulated in-place (STS.128 source)
        float4 acc[4];
        #pragma unroll
        for (int i2 = 0; i2 < 4; ++i2) acc[i2] = make_float4(0.f,0.f,0.f,0.f);

        #pragma unroll
        for (int q = 0; q < 7; ++q) {        // 7 x LDS.128 = 14 taps
            float4 pr = rp4[q];              // {x0,y0,x1,y1} = taps 2q, 2q+1
            #pragma unroll
            for (int h = 0; h < 2; ++h) {
                const int p = 2*q + h;
                float vx = h ? pr.z : pr.x;
                float vy = h ? pr.w : pr.y;
                float s  = fmaf(vy, vy, vx * vx);
                float xy = vx * vy;
                #pragma unroll
                for (int i2 = 0; i2 < 4; ++i2) {
                    int k = p - i2;
                    if (k >= 0 && k <= 10) {
                        acc[i2].x = fmaf(vx, wk(k), acc[i2].x);
                        acc[i2].y = fmaf(vy, wk(k), acc[i2].y);
                        acc[i2].z = fmaf(s,  wk(k), acc[i2].z);
                        acc[i2].w = fmaf(xy, wk(k), acc[i2].w);
                    }
                }
            }
        }

        float4* hp = hb4 + row * HBS + 4*gq;
        #pragma unroll
        for (int i2 = 0; i2 < 4; ++i2)
            hp[i2] = acc[i2];
    }
    __syncthreads();

    // ---------------- Stage 3: vertical 11-tap, 4-row block, LDS.128 taps -
    // 32 cols x 8 segments = 256 tasks on threads 0..255 (256/384 active).
    if (tid < 256) {
        const int col = tid & 31;
        const int r0  = (tid >> 5) * 4;     // 8 segments * 4 rows = 32

        float b0[4] = {0,0,0,0}, b1[4] = {0,0,0,0},
              b2[4] = {0,0,0,0}, b3[4] = {0,0,0,0};

        const float4* hp = hb4 + r0 * HBS + col;
        #pragma unroll
        for (int p = 0; p < 14; ++p) {
            float4 h = hp[p * HBS];          // one LDS.128: all 4 quantities
            #pragma unroll
            for (int i2 = 0; i2 < 4; ++i2) {
                int k = p - i2;
                if (k >= 0 && k <= 10) {
                    b0[i2] = fmaf(h.x, wk(k), b0[i2]);
                    b1[i2] = fmaf(h.y, wk(k), b1[i2]);
                    b2[i2] = fmaf(h.z, wk(k), b2[i2]);
                    b3[i2] = fmaf(h.w, wk(k), b3[i2]);
                }
            }
        }

        float* op = out + (size_t)plane * PLANE
                        + (size_t)(by * TH + r0) * IMG
                        + bx * TW + col;

        #pragma unroll
        for (int i2 = 0; i2 < 4; ++i2) {
            float mu1  = b0[i2];
            float mu2  = b1[i2];
            float m12  = mu1 * mu2;
            float m11  = mu1 * mu1;
            float m22  = mu2 * mu2;
            float ssum = b2[i2] - m11 - m22;    // sigma1^2 + sigma2^2
            float s12  = b3[i2] - m12;
            float num = fmaf(2.f, m12, SSIM_C1) * fmaf(2.f, s12, SSIM_C2);
            float den = (m11 + m22 + SSIM_C1) * (ssum + SSIM_C2);
            op[(size_t)i2 * IMG] = __fdividef(num, den);
        }
    }
}

extern "C" void kernel_launch(void* const* d_in, const int* in_sizes, int n_in,
                              void* d_out, int out_size)
{
    const float* x = (const float*)d_in[0];   // img_out  [16,3,512,512] f32
    const float* y = (const float*)d_in[1];   // img_target
    float* out = (float*)d_out;

    int planes = in_sizes[0] / PLANE;         // 48

    cudaFuncSetAttribute(ssim_kernel,
                         cudaFuncAttributeMaxDynamicSharedMemorySize,
                         SMEM_BYTES);

    dim3 grid(IMG / TW, IMG / TH, planes);    // (16, 16, 48)
    ssim_kernel<<<grid, NT, SMEM_BYTES>>>(x, y, out);
}